// round 4
// baseline (speedup 1.0000x reference)
#include <cuda_runtime.h>
#include <cuda_bf16.h>
#include <cuda_fp16.h>
#include <cuda_fp8.h>
#include <cstdint>

#define N_ROWS      12288        // L1_INPUT_SIZE
#define N_COLS      1030         // L1_OUTPUT_SIZE
#define HID         1024
#define STRIDE8     1032         // padded fp8 row stride bytes (8B aligned) — best measured
#define BATCH       8192
#define NFEAT       32
#define L2IN        2048
#define W_SCALE     128.0f       // weight scale into e4m3 normal range
#define INV_SCALE   0.0078125f   // 1/128
#define PSQT_K      0.08f        // 0.5 / (400/64)
#define GPR         258          // groups of 4 cols converted per row
#define ROWS_PER_CTA 4

// fp8(e4m3) copy of W1*128 (module-static, no runtime alloc)
__device__ unsigned char g_W1f8[(size_t)N_ROWS * STRIDE8];

// ---------------------------------------------------------------------------
// W1 fp32 -> fp8 conversion (runs every launch; deterministic)
// ---------------------------------------------------------------------------
__global__ void convert_kernel(const float* __restrict__ W1) {
    int gid = blockIdx.x * blockDim.x + threadIdx.x;
    if (gid >= N_ROWS * GPR) return;
    const int r   = gid / GPR;
    const int g   = gid - r * GPR;
    const int col = g * 4;
    const float* src = W1 + (size_t)r * N_COLS + col;

    float4 w;
    if (col + 4 <= N_COLS) {
        const float2 a = *reinterpret_cast<const float2*>(src);
        const float2 b = *reinterpret_cast<const float2*>(src + 2);
        w = make_float4(a.x, a.y, b.x, b.y);
    } else {
        w.x = (col + 0 < N_COLS) ? src[0] : 0.f;
        w.y = (col + 1 < N_COLS) ? src[1] : 0.f;
        w.z = (col + 2 < N_COLS) ? src[2] : 0.f;
        w.w = (col + 3 < N_COLS) ? src[3] : 0.f;
    }
    const __nv_fp8x2_storage_t lo =
        __nv_cvt_float2_to_fp8x2(make_float2(w.x * W_SCALE, w.y * W_SCALE),
                                 __NV_SATFINITE, __NV_E4M3);
    const __nv_fp8x2_storage_t hi =
        __nv_cvt_float2_to_fp8x2(make_float2(w.z * W_SCALE, w.w * W_SCALE),
                                 __NV_SATFINITE, __NV_E4M3);
    const uint32_t packed = (uint32_t)lo | ((uint32_t)hi << 16);
    *reinterpret_cast<uint32_t*>(g_W1f8 + (size_t)r * STRIDE8 + col) = packed;
}

// ---------------------------------------------------------------------------
// unpack u32 (4×e4m3) -> two half2, fused multiply-accumulate with vh
// ---------------------------------------------------------------------------
__device__ __forceinline__ void fma4_fp8(half2& a0, half2& a1, uint32_t w, half2 vh) {
    uint32_t h0, h1;
    asm("{\n\t"
        ".reg .b16 lo, hi;\n\t"
        "mov.b32 {lo, hi}, %2;\n\t"
        "cvt.rn.f16x2.e4m3x2 %0, lo;\n\t"
        "cvt.rn.f16x2.e4m3x2 %1, hi;\n\t"
        "}" : "=r"(h0), "=r"(h1) : "r"(w));
    a0 = __hfma2(*reinterpret_cast<half2*>(&h0), vh, a0);
    a1 = __hfma2(*reinterpret_cast<half2*>(&h1), vh, a1);
}

// ---------------------------------------------------------------------------
// Main fused kernel: one CTA per 4 batch rows, 128 threads.
// Per row: thread t owns fp8 columns [8t,8t+8) of both x and y hidden vectors.
// ---------------------------------------------------------------------------
__global__ __launch_bounds__(128)
void fwd_kernel(const int*   __restrict__ x,
                const int*   __restrict__ y,
                const float* __restrict__ v,
                const int*   __restrict__ s,
                const float* __restrict__ b1,
                const float* __restrict__ W2,
                const float* __restrict__ b2,
                float*       __restrict__ out)
{
    // record: {offx_bytes, offy_bytes, v as half2 bits, v as float bits}
    __shared__ uint4 srec[ROWS_PER_CTA][NFEAT];
    __shared__ float red[4][ROWS_PER_CTA];     // [warp][row]
    __shared__ int   sss[ROWS_PER_CTA];

    const int b0 = blockIdx.x * ROWS_PER_CTA;
    const int t  = threadIdx.x;

    // ---- prologue: 128 threads build all 4x32 records in one pass ----
    {
        const int row = t >> 5;
        const int a   = t & 31;
        const int gi  = (b0 + row) * NFEAT + a;
        const int offx = x[gi] * STRIDE8;
        const int offy = y[gi] * STRIDE8;
        const float vv = v[gi];
        const half2 vh = __float2half2_rn(vv);
        srec[row][a] = make_uint4((unsigned)offx, (unsigned)offy,
                                  *reinterpret_cast<const unsigned*>(&vh),
                                  __float_as_uint(vv));
        if (a == 0) sss[row] = s[b0 + row];
    }
    __syncthreads();

    const size_t toff = (size_t)t * 8;

#pragma unroll 1
    for (int r = 0; r < ROWS_PER_CTA; ++r) {
        const uint4* rec = srec[r];
        const int ss = sss[r];

        half2 ax[4], ay[4];
#pragma unroll
        for (int j = 0; j < 4; ++j) { ax[j] = __float2half2_rn(0.f); ay[j] = __float2half2_rn(0.f); }

#pragma unroll 4
        for (int a = 0; a < NFEAT; ++a) {
            const uint4 R = rec[a];
            half2 vh; *reinterpret_cast<unsigned*>(&vh) = R.z;
            const uint2 wx = *reinterpret_cast<const uint2*>(g_W1f8 + R.x + toff);
            const uint2 wy = *reinterpret_cast<const uint2*>(g_W1f8 + R.y + toff);
            fma4_fp8(ax[0], ax[1], wx.x, vh);
            fma4_fp8(ax[2], ax[3], wx.y, vh);
            fma4_fp8(ay[0], ay[1], wy.x, vh);
            fma4_fp8(ay[2], ay[3], wy.y, vh);
        }

        // ---- epilogue: relu(acc/128 + b1) dot W2[ss] ----
        const int col0 = t * 8;
        const float4 b1a = *reinterpret_cast<const float4*>(b1 + col0);
        const float4 b1b = *reinterpret_cast<const float4*>(b1 + col0 + 4);
        const float* w2row = W2 + (size_t)ss * L2IN;
        const float4 wxa = *reinterpret_cast<const float4*>(w2row + col0);
        const float4 wxb = *reinterpret_cast<const float4*>(w2row + col0 + 4);
        const float4 wya = *reinterpret_cast<const float4*>(w2row + HID + col0);
        const float4 wyb = *reinterpret_cast<const float4*>(w2row + HID + col0 + 4);

        const float2 fx0 = __half22float2(ax[0]);
        const float2 fx1 = __half22float2(ax[1]);
        const float2 fx2 = __half22float2(ax[2]);
        const float2 fx3 = __half22float2(ax[3]);
        const float2 fy0 = __half22float2(ay[0]);
        const float2 fy1 = __half22float2(ay[1]);
        const float2 fy2 = __half22float2(ay[2]);
        const float2 fy3 = __half22float2(ay[3]);

        float local = 0.f;
        local = fmaf(fmaxf(fmaf(fx0.x, INV_SCALE, b1a.x), 0.f), wxa.x, local);
        local = fmaf(fmaxf(fmaf(fx0.y, INV_SCALE, b1a.y), 0.f), wxa.y, local);
        local = fmaf(fmaxf(fmaf(fx1.x, INV_SCALE, b1a.z), 0.f), wxa.z, local);
        local = fmaf(fmaxf(fmaf(fx1.y, INV_SCALE, b1a.w), 0.f), wxa.w, local);
        local = fmaf(fmaxf(fmaf(fx2.x, INV_SCALE, b1b.x), 0.f), wxb.x, local);
        local = fmaf(fmaxf(fmaf(fx2.y, INV_SCALE, b1b.y), 0.f), wxb.y, local);
        local = fmaf(fmaxf(fmaf(fx3.x, INV_SCALE, b1b.z), 0.f), wxb.z, local);
        local = fmaf(fmaxf(fmaf(fx3.y, INV_SCALE, b1b.w), 0.f), wxb.w, local);

        local = fmaf(fmaxf(fmaf(fy0.x, INV_SCALE, b1a.x), 0.f), wya.x, local);
        local = fmaf(fmaxf(fmaf(fy0.y, INV_SCALE, b1a.y), 0.f), wya.y, local);
        local = fmaf(fmaxf(fmaf(fy1.x, INV_SCALE, b1a.z), 0.f), wya.z, local);
        local = fmaf(fmaxf(fmaf(fy1.y, INV_SCALE, b1a.w), 0.f), wya.w, local);
        local = fmaf(fmaxf(fmaf(fy2.x, INV_SCALE, b1b.x), 0.f), wyb.x, local);
        local = fmaf(fmaxf(fmaf(fy2.y, INV_SCALE, b1b.y), 0.f), wyb.y, local);
        local = fmaf(fmaxf(fmaf(fy3.x, INV_SCALE, b1b.z), 0.f), wyb.z, local);
        local = fmaf(fmaxf(fmaf(fy3.y, INV_SCALE, b1b.w), 0.f), wyb.w, local);

        // ---- psqt term: (x2 - y2) * PSQT_K ; b1 cancels in the difference ----
        if (t < 64) {
            const int a  = t & 31;
            const int sp = t >> 5;               // 0 = x, 1 = y
            const uint4 R = rec[a];
            const unsigned off = sp ? R.y : R.x;
            const unsigned char wb = g_W1f8[(size_t)off + HID + ss];
            const float w = __half2float(
                __nv_cvt_fp8_to_halfraw((__nv_fp8_storage_t)wb, __NV_E4M3));
            const float p = __uint_as_float(R.w) * w * (PSQT_K * INV_SCALE);
            local += sp ? -p : p;
        }

        // ---- warp reduction, stash per-warp partial for this row ----
#pragma unroll
        for (int o = 16; o > 0; o >>= 1)
            local += __shfl_down_sync(0xffffffffu, local, o);
        if ((t & 31) == 0) red[t >> 5][r] = local;
    }

    __syncthreads();
    if (t < ROWS_PER_CTA) {
        const float c = red[0][t] + red[1][t] + red[2][t] + red[3][t] + b2[sss[t]];
        out[b0 + t] = 1.0f / (1.0f + expf(-c));
    }
}

// ---------------------------------------------------------------------------
extern "C" void kernel_launch(void* const* d_in, const int* in_sizes, int n_in,
                              void* d_out, int out_size)
{
    const int*   x  = (const int*)  d_in[0];
    const int*   y  = (const int*)  d_in[1];
    const float* v  = (const float*)d_in[2];
    const int*   s  = (const int*)  d_in[3];
    const float* W1 = (const float*)d_in[4];
    const float* b1 = (const float*)d_in[5];
    const float* W2 = (const float*)d_in[6];
    const float* b2 = (const float*)d_in[7];
    float* out = (float*)d_out;

    const int total = N_ROWS * GPR;
    convert_kernel<<<(total + 255) / 256, 256>>>(W1);
    fwd_kernel<<<BATCH / ROWS_PER_CTA, 128>>>(x, y, v, s, b1, W2, b2, out);
}

// round 5
// speedup vs baseline: 1.1948x; 1.1948x over previous
#include <cuda_runtime.h>
#include <cuda_bf16.h>
#include <cuda_fp16.h>
#include <cuda_fp8.h>
#include <cstdint>

#define N_ROWS      12288        // L1_INPUT_SIZE
#define N_COLS      1030         // L1_OUTPUT_SIZE
#define HID         1024
#define STRIDE8     1152         // padded fp8 row stride bytes (128B multiple)
#define BATCH       8192
#define NFEAT       32
#define L2IN        2048
#define W_SCALE     128.0f       // weight scale into e4m3 normal range
#define INV_SCALE   0.0078125f   // 1/128
#define PSQT_K      0.08f        // 0.5 / (400/64)
#define GPR         258          // groups of 4 cols converted per row (covers 1030, pads to 1032)
#define ROWS_PER_CTA 2

// fp8(e4m3) copy of W1*128, 128B-aligned rows (module-static, no runtime alloc)
__device__ __align__(128) unsigned char g_W1f8[(size_t)N_ROWS * STRIDE8];

// ---------------------------------------------------------------------------
// W1 fp32 -> fp8 conversion (runs every launch; deterministic)
// ---------------------------------------------------------------------------
__global__ void convert_kernel(const float* __restrict__ W1) {
    int gid = blockIdx.x * blockDim.x + threadIdx.x;
    if (gid >= N_ROWS * GPR) return;
    const int r   = gid / GPR;
    const int g   = gid - r * GPR;
    const int col = g * 4;
    const float* src = W1 + (size_t)r * N_COLS + col;

    float4 w;
    if (col + 4 <= N_COLS) {
        const float2 a = *reinterpret_cast<const float2*>(src);
        const float2 b = *reinterpret_cast<const float2*>(src + 2);
        w = make_float4(a.x, a.y, b.x, b.y);
    } else {
        w.x = (col + 0 < N_COLS) ? src[0] : 0.f;
        w.y = (col + 1 < N_COLS) ? src[1] : 0.f;
        w.z = (col + 2 < N_COLS) ? src[2] : 0.f;
        w.w = (col + 3 < N_COLS) ? src[3] : 0.f;
    }
    const __nv_fp8x2_storage_t lo =
        __nv_cvt_float2_to_fp8x2(make_float2(w.x * W_SCALE, w.y * W_SCALE),
                                 __NV_SATFINITE, __NV_E4M3);
    const __nv_fp8x2_storage_t hi =
        __nv_cvt_float2_to_fp8x2(make_float2(w.z * W_SCALE, w.w * W_SCALE),
                                 __NV_SATFINITE, __NV_E4M3);
    const uint32_t packed = (uint32_t)lo | ((uint32_t)hi << 16);
    *reinterpret_cast<uint32_t*>(g_W1f8 + (size_t)r * STRIDE8 + col) = packed;
}

// ---------------------------------------------------------------------------
// unpack u32 (4×e4m3) -> two half2, fused multiply-accumulate with vh
// ---------------------------------------------------------------------------
__device__ __forceinline__ void fma4_fp8(half2& a0, half2& a1, uint32_t w, half2 vh) {
    uint32_t h0, h1;
    asm("{\n\t"
        ".reg .b16 lo, hi;\n\t"
        "mov.b32 {lo, hi}, %2;\n\t"
        "cvt.rn.f16x2.e4m3x2 %0, lo;\n\t"
        "cvt.rn.f16x2.e4m3x2 %1, hi;\n\t"
        "}" : "=r"(h0), "=r"(h1) : "r"(w));
    a0 = __hfma2(*reinterpret_cast<half2*>(&h0), vh, a0);
    a1 = __hfma2(*reinterpret_cast<half2*>(&h1), vh, a1);
}

// ---------------------------------------------------------------------------
// Main fused kernel: 128 threads = 2 batch rows, all parallel.
// Warps 0,1 -> row 0 ; warps 2,3 -> row 1. Within a row's warp pair, warp-half
// h owns hidden cols [h*512, h*512+512); lane L owns 16 fp8 cols per side.
// ---------------------------------------------------------------------------
__global__ __launch_bounds__(128, 8)
void fwd_kernel(const int*   __restrict__ x,
                const int*   __restrict__ y,
                const float* __restrict__ v,
                const int*   __restrict__ s,
                const float* __restrict__ b1,
                const float* __restrict__ W2,
                const float* __restrict__ b2,
                float*       __restrict__ out)
{
    // record: {offx_bytes, offy_bytes, v as half2 bits, v as float bits}
    __shared__ uint4 srec[ROWS_PER_CTA][NFEAT];
    __shared__ int   sss[ROWS_PER_CTA];
    __shared__ float red[4];

    const int b0 = blockIdx.x * ROWS_PER_CTA;
    const int t  = threadIdx.x;

    // ---- prologue: threads 0..63 build the 2x32 records ----
    if (t < 64) {
        const int row = t >> 5;
        const int a   = t & 31;
        const int gi  = (b0 + row) * NFEAT + a;
        const int offx = x[gi] * STRIDE8;
        const int offy = y[gi] * STRIDE8;
        const float vv = v[gi];
        const half2 vh = __float2half2_rn(vv);
        srec[row][a] = make_uint4((unsigned)offx, (unsigned)offy,
                                  *reinterpret_cast<const unsigned*>(&vh),
                                  __float_as_uint(vv));
    } else if (t < 64 + ROWS_PER_CTA) {
        sss[t - 64] = s[b0 + (t - 64)];
    }
    __syncthreads();

    const int w    = t >> 5;          // warp id 0..3
    const int L    = t & 31;          // lane
    const int row  = w >> 1;          // batch row within CTA
    const int h    = w & 1;           // column half
    const int col0 = h * 512 + L * 16;
    const unsigned char* basep = g_W1f8 + col0;
    const uint4* rec = srec[row];

    half2 ax[8], ay[8];
#pragma unroll
    for (int j = 0; j < 8; ++j) { ax[j] = __float2half2_rn(0.f); ay[j] = __float2half2_rn(0.f); }

#pragma unroll 2
    for (int a = 0; a < NFEAT; ++a) {
        const uint4 R = rec[a];
        half2 vh; *reinterpret_cast<unsigned*>(&vh) = R.z;
        const uint4 wx = *reinterpret_cast<const uint4*>(basep + R.x);
        const uint4 wy = *reinterpret_cast<const uint4*>(basep + R.y);
        fma4_fp8(ax[0], ax[1], wx.x, vh);
        fma4_fp8(ax[2], ax[3], wx.y, vh);
        fma4_fp8(ax[4], ax[5], wx.z, vh);
        fma4_fp8(ax[6], ax[7], wx.w, vh);
        fma4_fp8(ay[0], ay[1], wy.x, vh);
        fma4_fp8(ay[2], ay[3], wy.y, vh);
        fma4_fp8(ay[4], ay[5], wy.z, vh);
        fma4_fp8(ay[6], ay[7], wy.w, vh);
    }

    // ---- epilogue: relu(acc/128 + b1) dot W2[ss] over this thread's 16 cols/side ----
    const int ss = sss[row];
    const float* b1seg = b1 + col0;
    const float* w2x   = W2 + (size_t)ss * L2IN + col0;
    const float* w2y   = w2x + HID;

    float local = 0.f;
#pragma unroll
    for (int j = 0; j < 4; ++j) {
        const float4 bb  = reinterpret_cast<const float4*>(b1seg)[j];
        const float4 wwx = reinterpret_cast<const float4*>(w2x)[j];
        const float4 wwy = reinterpret_cast<const float4*>(w2y)[j];
        const float2 fx0 = __half22float2(ax[2 * j]);
        const float2 fx1 = __half22float2(ax[2 * j + 1]);
        const float2 fy0 = __half22float2(ay[2 * j]);
        const float2 fy1 = __half22float2(ay[2 * j + 1]);
        local = fmaf(fmaxf(fmaf(fx0.x, INV_SCALE, bb.x), 0.f), wwx.x, local);
        local = fmaf(fmaxf(fmaf(fx0.y, INV_SCALE, bb.y), 0.f), wwx.y, local);
        local = fmaf(fmaxf(fmaf(fx1.x, INV_SCALE, bb.z), 0.f), wwx.z, local);
        local = fmaf(fmaxf(fmaf(fx1.y, INV_SCALE, bb.w), 0.f), wwx.w, local);
        local = fmaf(fmaxf(fmaf(fy0.x, INV_SCALE, bb.x), 0.f), wwy.x, local);
        local = fmaf(fmaxf(fmaf(fy0.y, INV_SCALE, bb.y), 0.f), wwy.y, local);
        local = fmaf(fmaxf(fmaf(fy1.x, INV_SCALE, bb.z), 0.f), wwy.z, local);
        local = fmaf(fmaxf(fmaf(fy1.y, INV_SCALE, bb.w), 0.f), wwy.w, local);
    }

    // ---- psqt term: (x2 - y2) * PSQT_K ; b1 cancels in the difference ----
    // warp-half h==0 handles the x side (+), h==1 the y side (-): lane L = feature L
    {
        const uint4 R = rec[L];
        const unsigned off = h ? R.y : R.x;
        const unsigned char wb = g_W1f8[(size_t)off + HID + ss];
        const float wgt = __half2float(
            __nv_cvt_fp8_to_halfraw((__nv_fp8_storage_t)wb, __NV_E4M3));
        const float p = __uint_as_float(R.w) * wgt * (PSQT_K * INV_SCALE);
        local += h ? -p : p;
    }

    // ---- warp reduction, then 2-warp combine per row ----
#pragma unroll
    for (int o = 16; o > 0; o >>= 1)
        local += __shfl_down_sync(0xffffffffu, local, o);
    if (L == 0) red[w] = local;
    __syncthreads();
    if (t == 0)
        out[b0]     = 1.0f / (1.0f + expf(-(red[0] + red[1] + b2[sss[0]])));
    else if (t == 64)
        out[b0 + 1] = 1.0f / (1.0f + expf(-(red[2] + red[3] + b2[sss[1]])));
}

// ---------------------------------------------------------------------------
extern "C" void kernel_launch(void* const* d_in, const int* in_sizes, int n_in,
                              void* d_out, int out_size)
{
    const int*   x  = (const int*)  d_in[0];
    const int*   y  = (const int*)  d_in[1];
    const float* v  = (const float*)d_in[2];
    const int*   s  = (const int*)  d_in[3];
    const float* W1 = (const float*)d_in[4];
    const float* b1 = (const float*)d_in[5];
    const float* W2 = (const float*)d_in[6];
    const float* b2 = (const float*)d_in[7];
    float* out = (float*)d_out;

    const int total = N_ROWS * GPR;
    convert_kernel<<<(total + 255) / 256, 256>>>(W1);
    fwd_kernel<<<BATCH / ROWS_PER_CTA, 128>>>(x, y, v, s, b1, W2, b2, out);
}